// round 10
// baseline (speedup 1.0000x reference)
#include <cuda_runtime.h>
#include <cuda_bf16.h>
#include <math.h>

#define NSAMP 64
#define TLEN  512
#define DDIM  16
#define NDIAG 1023
#define BIGL  1.0e10f
#define LOG2E 1.4426950408889634f
#define LN2   0.6931471805599453f

// Scratch: D (pre-scaled by log2e) in diagonal-major layout: g_Ddiag[n][kk][ii]
__device__ float g_Ddiag[(size_t)NSAMP * 1024 * 512];   // 134 MB
__device__ float g_res[NSAMP];

__device__ __forceinline__ float ex2f(float x){ float y; asm("ex2.approx.ftz.f32 %0, %1;" : "=f"(y) : "f"(x)); return y; }
__device__ __forceinline__ float lg2f(float x){ float y; asm("lg2.approx.ftz.f32 %0, %1;" : "=f"(y) : "f"(x)); return y; }

// ---------------------------------------------------------------------------
// Kernel A: D[n,ii,jj] = ||X[n,ii]-Z[jj]||^2 * log2e, stored DIAGONAL-major.
// (unchanged — known good, ~65us)
// ---------------------------------------------------------------------------
__global__ void __launch_bounds__(512) compute_D_kernel(const float* __restrict__ X,
                                                        const float* __restrict__ Z)
{
    extern __shared__ float sm[];
    float* ts  = sm;                         // 64*514
    float* zsh = ts  + 64 * 514;             // 512*17
    float* z2s = zsh + 512 * 17;             // 512 (pre-scaled by LOG2E)
    float* xs  = z2s + 512;                  // 64*16

    const int n    = blockIdx.y;
    const int row0 = blockIdx.x * 64;
    const int tid  = threadIdx.x;
    const int w    = tid >> 5;
    const int lane = tid & 31;

    for (int i = tid; i < 512 * 16; i += 512)
        zsh[(i >> 4) * 17 + (i & 15)] = Z[i];
    const float* Xn = X + ((size_t)n * TLEN + row0) * DDIM;
    for (int i = tid; i < 64 * 16; i += 512)
        xs[i] = Xn[i];
    __syncthreads();

    {
        float s = 0.f;
        #pragma unroll
        for (int c = 0; c < 16; c++) { float v = zsh[tid * 17 + c]; s = fmaf(v, v, s); }
        z2s[tid] = s * LOG2E;
    }

    float xr[4][16], x2r[4];
    #pragma unroll
    for (int q = 0; q < 4; q++) {
        float s = 0.f;
        #pragma unroll
        for (int c = 0; c < 16; c++) {
            float v = xs[(w * 4 + q) * 16 + c];
            xr[q][c] = v; s = fmaf(v, v, s);
        }
        x2r[q] = s * LOG2E;
    }
    __syncthreads();

    #pragma unroll 1
    for (int t = 0; t < 16; t++) {
        const int jj = lane + 32 * t;
        float zr[16];
        #pragma unroll
        for (int c = 0; c < 16; c++) zr[c] = zsh[jj * 17 + c];
        const float z2v = z2s[jj];
        #pragma unroll
        for (int q = 0; q < 4; q++) {
            float acc = 0.f;
            #pragma unroll
            for (int c = 0; c < 16; c++) acc = fmaf(xr[q][c], zr[c], acc);
            ts[(w * 4 + q) * 514 + jj] = fmaxf(fmaf(acc, -2.0f * LOG2E, x2r[q] + z2v), 0.0f);
        }
    }
    __syncthreads();

    const size_t base = (size_t)n * (1024 * 512);
    for (int kkoff = w; kkoff < 575; kkoff += 16) {
        const int kk   = row0 + kkoff;
        const int iilo = max(row0, kk - 511);
        const int iihi = min(row0 + 63, kk);
        for (int ii = iilo + lane; ii <= iihi; ii += 32)
            g_Ddiag[base + (size_t)kk * 512 + ii] = ts[(ii - row0) * 514 + (kk - ii)];
    }
}

// ---------------------------------------------------------------------------
// Kernel B: log2-domain soft-DTW wavefront, STAIRCASE schedule.
// 256 threads = 8 warps = 2 warps/SMSP (latency hiding), 2 cells/thread.
// Warp w lags warp w-1 by 8 diagonals; one __syncthreads per 8 diagonals.
// Ring safety (lag 8): reader slots and same-phase writer slots span 17 < 32.
// ---------------------------------------------------------------------------
#define NPHASE 135   // warp 7 reaches diag 1022 at phase 134 (j=6)

__global__ void __launch_bounds__(256) dp_kernel()
{
    const int n    = blockIdx.x;
    const int tid  = threadIdx.x;
    const int w    = tid >> 5;
    const int lane = tid & 31;

    __shared__ float rings[9][32];     // warp w reads rings[w], writes rings[w+1]
    for (int i = tid; i < 9 * 32; i += 256) (&rings[0][0])[i] = BIGL;

    float rc0 = BIGL, rc1 = BIGL;
    float rd0 = BIGL, rd1 = BIGL;
    if (tid == 0) rd0 = 0.0f;          // corner R[0][0]
    float resv = BIGL;                 // snapshot of rc1 at diag 1022

    const float2* __restrict__ Dn2 = (const float2*)(g_Ddiag + (size_t)n * (1024 * 512));
    float2 dbuf[8];
    #pragma unroll
    for (int j = 0; j < 8; j++) {
        int idx = j - 8 * w; idx = idx < 0 ? 0 : idx;
        dbuf[j] = Dn2[(size_t)idx * 256 + tid];
    }

    const int row0 = 2 * tid;          // first of this thread's 2 rows
    float* ringr = &rings[w][0];       // read ring (warp 0 -> all-BIGL row)
    float* ringw = &rings[w + 1][0];   // write ring
    __syncthreads();

#define DP_STEP(KK, D2)                                                        \
    {                                                                          \
        const int kkq = (KK);                                                  \
        const float bval = ringr[(kkq - 1) & 31];   /* uniform LDS, off-chain */ \
        float upsh = __shfl_up_sync(0xffffffffu, rc1, 1);                      \
        const float u0 = (lane == 0) ? bval : upsh;                            \
        const float u1 = rc0;                                                  \
        {                                                                      \
            float m  = fminf(fminf(u0, rc0), rd0);                             \
            float Mx = fmaxf(fmaxf(u0, rc0), rd0);                             \
            float mid = ((u0 + rc0) + rd0) - m - Mx;                           \
            float s  = 1.0f + ex2f(m - mid) + ex2f(m - Mx);                    \
            float v  = ((D2).x + m) - lg2f(s);                                 \
            if ((unsigned)(kkq - (row0 + 0)) >= 512u) v = BIGL;                \
            rd0 = u0; rc0 = v;                                                 \
        }                                                                      \
        {                                                                      \
            float m  = fminf(fminf(u1, rc1), rd1);                             \
            float Mx = fmaxf(fmaxf(u1, rc1), rd1);                             \
            float mid = ((u1 + rc1) + rd1) - m - Mx;                           \
            float s  = 1.0f + ex2f(m - mid) + ex2f(m - Mx);                    \
            float v  = ((D2).y + m) - lg2f(s);                                 \
            if ((unsigned)(kkq - (row0 + 1)) >= 512u) v = BIGL;                \
            rd1 = u1; rc1 = v;                                                 \
        }                                                                      \
        if (kkq == NDIAG - 1) resv = rc1;          /* snapshot before overrun */ \
        if (lane == 31 && (unsigned)kkq < 1023u) ringw[kkq & 31] = rc1;        \
    }

    #pragma unroll 1
    for (int p = 0; p < NPHASE; ++p) {
        const int kwb = 8 * p - 8 * w;         // this warp's diag at j=0
        #pragma unroll
        for (int j = 0; j < 8; j++) {
            const int cur = kwb + j;
            DP_STEP(cur, dbuf[j]);
            int nid = cur + 8;                 // branchless clamped prefetch
            nid = nid < 0 ? 0 : (nid > 1022 ? 1022 : nid);
            dbuf[j] = Dn2[(size_t)nid * 256 + tid];
        }
        __syncthreads();
    }
#undef DP_STEP

    if (tid == 255) g_res[n] = resv * LN2;     // row 511 at diag 1022: R[T,T]
}

// ---------------------------------------------------------------------------
// Kernel C: deterministic weighted reduction.
// ---------------------------------------------------------------------------
__global__ void reduce_kernel(const float* __restrict__ wts, float* __restrict__ out)
{
    __shared__ float s[64];
    const int tid = threadIdx.x;
    s[tid] = g_res[tid] * wts[tid];
    __syncthreads();
    #pragma unroll
    for (int off = 32; off > 0; off >>= 1) {
        if (tid < off) s[tid] += s[tid + off];
        __syncthreads();
    }
    if (tid == 0) out[0] = s[0];
}

// ---------------------------------------------------------------------------
extern "C" void kernel_launch(void* const* d_in, const int* in_sizes, int n_in,
                              void* d_out, int out_size)
{
    const float* X = nullptr; const float* wts = nullptr; const float* Z = nullptr;
    for (int i = 0; i < n_in; i++) {
        if      (in_sizes[i] == NSAMP)        wts = (const float*)d_in[i];
        else if (in_sizes[i] == TLEN * DDIM)  Z   = (const float*)d_in[i];
        else                                  X   = (const float*)d_in[i];
    }
    float* out = (float*)d_out;

    const int smemA = (64 * 514 + 512 * 17 + 512 + 64 * 16) * (int)sizeof(float); // 172544
    cudaFuncSetAttribute(compute_D_kernel, cudaFuncAttributeMaxDynamicSharedMemorySize, smemA);

    compute_D_kernel<<<dim3(8, NSAMP), 512, smemA>>>(X, Z);
    dp_kernel<<<NSAMP, 256>>>();
    reduce_kernel<<<1, 64>>>(wts, out);
}

// round 11
// speedup vs baseline: 2.2914x; 2.2914x over previous
#include <cuda_runtime.h>
#include <cuda_bf16.h>
#include <math.h>

#define NSAMP 64
#define TLEN  512
#define DDIM  16
#define NDIAG 1023
#define BIGL  1.0e10f
#define LOG2E 1.4426950408889634f
#define LN2   0.6931471805599453f
#define NPHASE 131

__device__ float g_res[NSAMP];

typedef unsigned long long ull;

__device__ __forceinline__ float ex2f(float x){ float y; asm("ex2.approx.ftz.f32 %0, %1;" : "=f"(y) : "f"(x)); return y; }
__device__ __forceinline__ float lg2f(float x){ float y; asm("lg2.approx.ftz.f32 %0, %1;" : "=f"(y) : "f"(x)); return y; }
__device__ __forceinline__ ull mul2(ull a, ull b){ ull d; asm("mul.rn.f32x2 %0, %1, %2;" : "=l"(d) : "l"(a), "l"(b)); return d; }
__device__ __forceinline__ ull add2(ull a, ull b){ ull d; asm("add.rn.f32x2 %0, %1, %2;" : "=l"(d) : "l"(a), "l"(b)); return d; }
__device__ __forceinline__ ull fma2(ull a, ull b, ull c){ ull d; asm("fma.rn.f32x2 %0, %1, %2, %3;" : "=l"(d) : "l"(a), "l"(b), "l"(c)); return d; }
#define UNPK(LO, HI, P) asm("mov.b64 {%0, %1}, %2;" : "=f"(LO), "=f"(HI) : "l"(P))

// ---------------------------------------------------------------------------
// FUSED kernel: per-CTA (1 sample) soft-DTW with on-the-fly D computation.
// 128 threads = 4 warps (1/SMSP), 4 cells/thread (rows 4t..4t+3).
// Staircase schedule (lag 8) + rings: identical to the proven R9 DP core.
// D[kk+1] computed during step kk from a 4-row Z register cache; one new Z
// row per diagonal via conflict-free permuted smem (slot=(j>>2)+128*(j&3),
// 72B pitch). Dots use packed f32x2 FMA.
// ---------------------------------------------------------------------------
__global__ void __launch_bounds__(128) fused_dp_kernel(const float* __restrict__ X,
                                                       const float* __restrict__ Z)
{
    __shared__ float zsm[512 * 18];    // permuted Z rows: 16 data + z2*log2e + pad
    __shared__ float rings[5][32];     // warp w reads rings[w], writes rings[w+1]

    const int n    = blockIdx.x;
    const int tid  = threadIdx.x;
    const int w    = tid >> 5;
    const int lane = tid & 31;
    const int row0 = 4 * tid;

    // ---- stage Z into permuted smem slots (+ z2*log2e at offset 16) ----
    for (int r = tid; r < 512; r += 128) {
        const float* zg = Z + r * 16;
        float vals[16]; float s2 = 0.f;
        #pragma unroll
        for (int k = 0; k < 16; k++) { float v = zg[k]; vals[k] = v; s2 = fmaf(v, v, s2); }
        float* dst = zsm + ((r >> 2) + 128 * (r & 3)) * 18;
        #pragma unroll
        for (int k = 0; k < 16; k++) dst[k] = vals[k];
        dst[16] = s2 * LOG2E;
    }
    for (int i = tid; i < 5 * 32; i += 128) (&rings[0][0])[i] = BIGL;

    // ---- stage X rows 4t..4t+3 into packed registers, compute x2*log2e ----
    ull xp[4][8]; float x2L[4];
    {
        const ull* Xp = (const ull*)(X + ((size_t)n * TLEN + row0) * DDIM);
        #pragma unroll
        for (int c = 0; c < 4; c++) {
            float s2 = 0.f;
            #pragma unroll
            for (int k = 0; k < 8; k++) {
                ull p = Xp[c * 8 + k]; xp[c][k] = p;
                float lo, hi; UNPK(lo, hi, p);
                s2 = fmaf(lo, lo, fmaf(hi, hi, s2));
            }
            x2L[c] = s2 * LOG2E;
        }
    }

    float rc0 = BIGL, rc1 = BIGL, rc2 = BIGL, rc3 = BIGL;
    float rd0 = BIGL, rd1 = BIGL, rd2 = BIGL, rd3 = BIGL;
    if (tid == 0) rd0 = 0.0f;          // corner R[0][0]
    float resv = BIGL;

    float* ringr = &rings[w][0];
    float* ringw = &rings[w + 1][0];

    __syncthreads();                   // zsm + rings visible to all warps

    ull   zr[4][8];                    // 4-row Z cache (slot = row index mod 4)
    float dD[2][4];                    // D ping-pong: dD[kk&1][cell]

// Load Z row (unclamped JUC) into register slot SLOT (compile-time).
#define ZLOAD(SLOT, JUC)                                                       \
    {                                                                          \
        int jc = (JUC); jc = jc < 0 ? 0 : (jc > 511 ? 511 : jc);               \
        const ull* zp = (const ull*)(zsm + ((jc >> 2) + 128 * (jc & 3)) * 18); \
        zr[SLOT][0] = zp[0]; zr[SLOT][1] = zp[1];                              \
        zr[SLOT][2] = zp[2]; zr[SLOT][3] = zp[3];                              \
        zr[SLOT][4] = zp[4]; zr[SLOT][5] = zp[5];                              \
        zr[SLOT][6] = zp[6]; zr[SLOT][7] = zp[7];                              \
    }

// D for cell C (row row0+C) against Z row JUC held in register slot SLOT.
#define DCOMP(DST, C, SLOT, JUC)                                               \
    {                                                                          \
        int jc = (JUC); jc = jc < 0 ? 0 : (jc > 511 ? 511 : jc);               \
        float z2v = zsm[((jc >> 2) + 128 * (jc & 3)) * 18 + 16];               \
        ull a0 = mul2(xp[C][0], zr[SLOT][0]);                                  \
        ull a1 = mul2(xp[C][1], zr[SLOT][1]);                                  \
        a0 = fma2(xp[C][2], zr[SLOT][2], a0);                                  \
        a1 = fma2(xp[C][3], zr[SLOT][3], a1);                                  \
        a0 = fma2(xp[C][4], zr[SLOT][4], a0);                                  \
        a1 = fma2(xp[C][5], zr[SLOT][5], a1);                                  \
        a0 = fma2(xp[C][6], zr[SLOT][6], a0);                                  \
        a1 = fma2(xp[C][7], zr[SLOT][7], a1);                                  \
        a0 = add2(a0, a1);                                                     \
        float lo, hi; UNPK(lo, hi, a0);                                        \
        float dot = lo + hi;                                                   \
        (DST) = fmaxf(fmaf(dot, -2.0f * LOG2E, x2L[C] + z2v), 0.0f);           \
    }

    // ---- prologue: prime Z cache + dD[0] for this warp's first diag ----
    const int kstart = -8 * w;         // ≡ 0 mod 8 → all slot indices compile-time
    ZLOAD(1, kstart - 3 - row0)
    ZLOAD(2, kstart - 2 - row0)
    ZLOAD(3, kstart - 1 - row0)
    ZLOAD(0, kstart + 0 - row0)
    DCOMP(dD[0][0], 0, 0, kstart - row0 - 0)
    DCOMP(dD[0][1], 1, 3, kstart - row0 - 1)
    DCOMP(dD[0][2], 2, 2, kstart - row0 - 2)
    DCOMP(dD[0][3], 3, 1, kstart - row0 - 3)
    ZLOAD(1, kstart + 1 - row0)        // evicts oldest; cache = rows kstart-2..kstart+1

// One DP step at diag cur = kwb + J (J literal 0..7). R9-verbatim softmin core.
#define DP_STEP(J)                                                             \
    {                                                                          \
        const int cur = kwb + (J);                                             \
        const float bval = ringr[(cur - 1) & 31];                              \
        float upsh = __shfl_up_sync(0xffffffffu, rc3, 1);                      \
        const float u0 = (lane == 0) ? bval : upsh;                            \
        const float u1 = rc0, u2 = rc1, u3 = rc2;                              \
        {                                                                      \
            float m  = fminf(fminf(u0, rc0), rd0);                             \
            float Mx = fmaxf(fmaxf(u0, rc0), rd0);                             \
            float mid = ((u0 + rc0) + rd0) - m - Mx;                           \
            float s  = 1.0f + ex2f(m - mid) + ex2f(m - Mx);                    \
            float v  = (dD[(J) & 1][0] + m) - lg2f(s);                         \
            if ((unsigned)(cur - (row0 + 0)) >= 512u) v = BIGL;                \
            rd0 = u0; rc0 = v;                                                 \
        }                                                                      \
        {                                                                      \
            float m  = fminf(fminf(u1, rc1), rd1);                             \
            float Mx = fmaxf(fmaxf(u1, rc1), rd1);                             \
            float mid = ((u1 + rc1) + rd1) - m - Mx;                           \
            float s  = 1.0f + ex2f(m - mid) + ex2f(m - Mx);                    \
            float v  = (dD[(J) & 1][1] + m) - lg2f(s);                         \
            if ((unsigned)(cur - (row0 + 1)) >= 512u) v = BIGL;                \
            rd1 = u1; rc1 = v;                                                 \
        }                                                                      \
        {                                                                      \
            float m  = fminf(fminf(u2, rc2), rd2);                             \
            float Mx = fmaxf(fmaxf(u2, rc2), rd2);                             \
            float mid = ((u2 + rc2) + rd2) - m - Mx;                           \
            float s  = 1.0f + ex2f(m - mid) + ex2f(m - Mx);                    \
            float v  = (dD[(J) & 1][2] + m) - lg2f(s);                         \
            if ((unsigned)(cur - (row0 + 2)) >= 512u) v = BIGL;                \
            rd2 = u2; rc2 = v;                                                 \
        }                                                                      \
        {                                                                      \
            float m  = fminf(fminf(u3, rc3), rd3);                             \
            float Mx = fmaxf(fmaxf(u3, rc3), rd3);                             \
            float mid = ((u3 + rc3) + rd3) - m - Mx;                           \
            float s  = 1.0f + ex2f(m - mid) + ex2f(m - Mx);                    \
            float v  = (dD[(J) & 1][3] + m) - lg2f(s);                         \
            if ((unsigned)(cur - (row0 + 3)) >= 512u) v = BIGL;                \
            rd3 = u3; rc3 = v;                                                 \
        }                                                                      \
        if (cur == NDIAG - 1) resv = rc3;                                      \
        if (lane == 31 && (unsigned)cur < 1023u) ringw[cur & 31] = rc3;        \
        /* fused: D for diag cur+1 (reads old slot (J-2)&3 BEFORE ZLOAD) */    \
        DCOMP(dD[((J) + 1) & 1][0], 0, ((J) + 1) & 3, cur + 1 - row0)          \
        DCOMP(dD[((J) + 1) & 1][1], 1, ((J) + 0) & 3, cur     - row0)          \
        DCOMP(dD[((J) + 1) & 1][2], 2, ((J) - 1) & 3, cur - 1 - row0)          \
        DCOMP(dD[((J) + 1) & 1][3], 3, ((J) - 2) & 3, cur - 2 - row0)          \
        ZLOAD(((J) + 2) & 3, cur + 2 - row0)                                   \
    }

    #pragma unroll 1
    for (int p = 0; p < NPHASE; ++p) {
        const int kwb = 8 * p - 8 * w;
        DP_STEP(0) DP_STEP(1) DP_STEP(2) DP_STEP(3)
        DP_STEP(4) DP_STEP(5) DP_STEP(6) DP_STEP(7)
        __syncthreads();
    }
#undef DP_STEP
#undef DCOMP
#undef ZLOAD

    if (tid == 127) g_res[n] = resv * LN2;     // row 511 at diag 1022: R[T,T]
}

// ---------------------------------------------------------------------------
// Deterministic weighted reduction.
// ---------------------------------------------------------------------------
__global__ void reduce_kernel(const float* __restrict__ wts, float* __restrict__ out)
{
    __shared__ float s[64];
    const int tid = threadIdx.x;
    s[tid] = g_res[tid] * wts[tid];
    __syncthreads();
    #pragma unroll
    for (int off = 32; off > 0; off >>= 1) {
        if (tid < off) s[tid] += s[tid + off];
        __syncthreads();
    }
    if (tid == 0) out[0] = s[0];
}

// ---------------------------------------------------------------------------
extern "C" void kernel_launch(void* const* d_in, const int* in_sizes, int n_in,
                              void* d_out, int out_size)
{
    const float* X = nullptr; const float* wts = nullptr; const float* Z = nullptr;
    for (int i = 0; i < n_in; i++) {
        if      (in_sizes[i] == NSAMP)        wts = (const float*)d_in[i];
        else if (in_sizes[i] == TLEN * DDIM)  Z   = (const float*)d_in[i];
        else                                  X   = (const float*)d_in[i];
    }
    float* out = (float*)d_out;

    fused_dp_kernel<<<NSAMP, 128>>>(X, Z);
    reduce_kernel<<<1, 64>>>(wts, out);
}